// round 1
// baseline (speedup 1.0000x reference)
#include <cuda_runtime.h>
#include <math.h>

// Problem constants (fixed by the reference)
#define B_  16
#define S_  8192
#define H_  512
#define M_  (B_ * S_)      // 131072 rows of the big GEMM
#define NSLICE 4           // N=512 split into 4 slices of 128

// ---------------- scratch (no allocations allowed) ----------------
__device__ float g_qproj[B_ * H_];            // (B,H) q @ W_q^T
__device__ float g_part[NSLICE][M_];          // partial score sums per N-slice (2 MB)
__device__ float g_ctxpart[64][B_][H_];       // context partial sums per s-chunk (2 MB)

// ---------------- kernel 1: q_proj[b,o] = dot(query[b,:], W_q[o,:]) ----------------
__global__ void qproj_kernel(const float* __restrict__ query,
                             const float* __restrict__ Wq)
{
    int w    = threadIdx.x >> 5;
    int lane = threadIdx.x & 31;
    int o    = blockIdx.x * 8 + w;     // gridDim.x = 64
    int b    = blockIdx.y;             // gridDim.y = 16
    const float* q  = query + b * H_;
    const float* wr = Wq + o * H_;
    float s = 0.f;
    #pragma unroll 4
    for (int k = lane; k < H_; k += 32) s += q[k] * wr[k];
    #pragma unroll
    for (int off = 16; off > 0; off >>= 1) s += __shfl_xor_sync(0xffffffffu, s, off);
    if (lane == 0) g_qproj[b * H_ + o] = s;
}

// ---------------- kernel 2: fused GEMM + tanh + v-reduce ----------------
// C[m,o] = sum_k enc[m,k] * Wh[o,k]   (both row-major, K contiguous -> NT gemm)
// g_part[bn][m] = sum_{o in slice bn} tanh(C[m,o] + qproj[b,o]) * v[o]
// Tile: 128x128x16, 256 threads, 8x8 per thread, FMAs as packed f32x2.
#define BM 128
#define BN 128
#define BK 16
#define LDS_PAD 136   // row stride in floats: 136%32==8 -> conflict-free transposed stores

__global__ __launch_bounds__(256, 2)
void score_gemm(const float* __restrict__ A,    // enc  (M_, 512)
                const float* __restrict__ Wh,   // (512, 512)
                const float* __restrict__ v)    // (512,)
{
    __shared__ __align__(16) float As[BK][LDS_PAD];
    __shared__ __align__(16) float Bs[BK][LDS_PAD];

    const int bm  = blockIdx.x;          // 1024 tiles over M
    const int bn  = blockIdx.y;          // 4 slices over N
    const int tid = threadIdx.x;
    const int tx  = tid & 15;
    const int ty  = tid >> 4;

    const float* Abase = A  + (size_t)bm * BM * H_;
    const float* Bbase = Wh + (size_t)bn * BN * H_;

    // 8 rows x 8 cols of C, columns packed in f32x2 pairs
    unsigned long long acc[8][4];
    #pragma unroll
    for (int i = 0; i < 8; i++)
        #pragma unroll
        for (int j = 0; j < 4; j++) acc[i][j] = 0ull;   // (0.f, 0.f)

    for (int k0 = 0; k0 < H_; k0 += BK) {
        // Load A tile (128x16) transposed into As[k][m]
        #pragma unroll
        for (int i = 0; i < 2; i++) {
            int id  = tid + i * 256;
            int row = id >> 2;
            int c4  = (id & 3) * 4;
            float4 t = *(const float4*)(Abase + (size_t)row * H_ + k0 + c4);
            As[c4 + 0][row] = t.x; As[c4 + 1][row] = t.y;
            As[c4 + 2][row] = t.z; As[c4 + 3][row] = t.w;
        }
        // Load B tile (128x16) transposed into Bs[k][n]
        #pragma unroll
        for (int i = 0; i < 2; i++) {
            int id  = tid + i * 256;
            int row = id >> 2;
            int c4  = (id & 3) * 4;
            float4 t = *(const float4*)(Bbase + (size_t)row * H_ + k0 + c4);
            Bs[c4 + 0][row] = t.x; Bs[c4 + 1][row] = t.y;
            Bs[c4 + 2][row] = t.z; Bs[c4 + 3][row] = t.w;
        }
        __syncthreads();

        #pragma unroll
        for (int kk = 0; kk < BK; kk++) {
            float4 a0 = *(const float4*)&As[kk][ty * 8];
            float4 a1 = *(const float4*)&As[kk][ty * 8 + 4];
            float a[8] = {a0.x, a0.y, a0.z, a0.w, a1.x, a1.y, a1.z, a1.w};
            // b pairs read directly as 64-bit (consecutive floats)
            ulonglong2 b01 = *(const ulonglong2*)&Bs[kk][tx * 8];
            ulonglong2 b23 = *(const ulonglong2*)&Bs[kk][tx * 8 + 4];
            unsigned long long bb[4] = {b01.x, b01.y, b23.x, b23.y};
            #pragma unroll
            for (int i = 0; i < 8; i++) {
                unsigned long long a2;
                asm("mov.b64 %0, {%1, %1};" : "=l"(a2) : "f"(a[i]));
                #pragma unroll
                for (int j = 0; j < 4; j++) {
                    asm("fma.rn.f32x2 %0, %1, %2, %0;"
                        : "+l"(acc[i][j]) : "l"(a2), "l"(bb[j]));
                }
            }
        }
        __syncthreads();
    }

    // Epilogue: tanh(C + qproj) * v, reduced over this block's 128 columns.
    const int b   = (bm * BM) >> 13;          // row block fits inside one batch (8192 % 128 == 0)
    const int c0  = bn * BN + tx * 8;
    float vr[8], qr[8];
    {
        float4 v0 = *(const float4*)(v + c0);
        float4 v1 = *(const float4*)(v + c0 + 4);
        vr[0]=v0.x; vr[1]=v0.y; vr[2]=v0.z; vr[3]=v0.w;
        vr[4]=v1.x; vr[5]=v1.y; vr[6]=v1.z; vr[7]=v1.w;
        float4 q0 = *(const float4*)(g_qproj + b * H_ + c0);
        float4 q1 = *(const float4*)(g_qproj + b * H_ + c0 + 4);
        qr[0]=q0.x; qr[1]=q0.y; qr[2]=q0.z; qr[3]=q0.w;
        qr[4]=q1.x; qr[5]=q1.y; qr[6]=q1.z; qr[7]=q1.w;
    }

    float rsum[8];
    #pragma unroll
    for (int i = 0; i < 8; i++) {
        float s = 0.f;
        #pragma unroll
        for (int j = 0; j < 4; j++) {
            float lo, hi;
            asm("mov.b64 {%0, %1}, %2;" : "=f"(lo), "=f"(hi) : "l"(acc[i][j]));
            s += tanhf(lo + qr[2 * j])     * vr[2 * j];
            s += tanhf(hi + qr[2 * j + 1]) * vr[2 * j + 1];
        }
        rsum[i] = s;
    }

    // Cross-thread reduce over the 16 column-groups (deterministic order).
    float* red = &As[0][0];                   // 2048 floats, smem reuse (synced above)
    #pragma unroll
    for (int i = 0; i < 8; i++) red[(ty * 8 + i) * 16 + tx] = rsum[i];
    __syncthreads();
    if (tid < 128) {
        float s = 0.f;
        #pragma unroll
        for (int t = 0; t < 16; t++) s += red[tid * 16 + t];
        g_part[bn][(size_t)bm * BM + tid] = s;
    }
}

// ---------------- kernel 3: softmax over S per batch, writes alpha ----------------
__global__ __launch_bounds__(1024)
void softmax_kernel(float* __restrict__ out_alpha)
{
    __shared__ float sm[32];
    const int b   = blockIdx.x;
    const int tid = threadIdx.x;
    const int w   = tid >> 5, lane = tid & 31;

    float sc[8];
    float mx = -1e30f;
    #pragma unroll
    for (int i = 0; i < 8; i++) {
        int m = b * S_ + tid + i * 1024;
        float x = g_part[0][m] + g_part[1][m] + g_part[2][m] + g_part[3][m];
        sc[i] = x;
        mx = fmaxf(mx, x);
    }
    #pragma unroll
    for (int off = 16; off > 0; off >>= 1) mx = fmaxf(mx, __shfl_xor_sync(0xffffffffu, mx, off));
    if (lane == 0) sm[w] = mx;
    __syncthreads();
    if (tid < 32) {
        float t = sm[tid];
        #pragma unroll
        for (int off = 16; off > 0; off >>= 1) t = fmaxf(t, __shfl_xor_sync(0xffffffffu, t, off));
        if (tid == 0) sm[0] = t;
    }
    __syncthreads();
    mx = sm[0];
    __syncthreads();

    float tot = 0.f;
    #pragma unroll
    for (int i = 0; i < 8; i++) { sc[i] = expf(sc[i] - mx); tot += sc[i]; }
    #pragma unroll
    for (int off = 16; off > 0; off >>= 1) tot += __shfl_xor_sync(0xffffffffu, tot, off);
    if (lane == 0) sm[w] = tot;
    __syncthreads();
    if (tid < 32) {
        float t = sm[tid];
        #pragma unroll
        for (int off = 16; off > 0; off >>= 1) t += __shfl_xor_sync(0xffffffffu, t, off);
        if (tid == 0) sm[0] = t;
    }
    __syncthreads();
    float inv = 1.f / sm[0];

    #pragma unroll
    for (int i = 0; i < 8; i++)
        out_alpha[b * S_ + tid + i * 1024] = sc[i] * inv;
}

// ---------------- kernel 4: context partial sums over s-chunks ----------------
__global__ __launch_bounds__(512)
void ctx_part_kernel(const float* __restrict__ enc,
                     const float* __restrict__ alpha)
{
    __shared__ float al[128];
    const int sch = blockIdx.x;       // 64 chunks of 128 rows
    const int b   = blockIdx.y;       // 16
    const int h   = threadIdx.x;      // 512
    const int s0  = sch * 128;
    if (threadIdx.x < 128) al[threadIdx.x] = alpha[b * S_ + s0 + threadIdx.x];
    __syncthreads();
    const float* e = enc + ((size_t)b * S_ + s0) * H_ + h;
    float acc = 0.f;
    #pragma unroll 8
    for (int s = 0; s < 128; s++) acc += al[s] * e[(size_t)s * H_];
    g_ctxpart[sch][b][h] = acc;
}

// ---------------- kernel 5: reduce context partials ----------------
__global__ __launch_bounds__(512)
void ctx_reduce_kernel(float* __restrict__ out_ctx)
{
    const int b = blockIdx.x, h = threadIdx.x;
    float s = 0.f;
    #pragma unroll
    for (int c = 0; c < 64; c++) s += g_ctxpart[c][b][h];
    out_ctx[b * H_ + h] = s;
}

// ---------------- launcher ----------------
extern "C" void kernel_launch(void* const* d_in, const int* in_sizes, int n_in,
                              void* d_out, int out_size)
{
    const float* enc   = (const float*)d_in[0];  // (B,S,H)
    const float* query = (const float*)d_in[1];  // (B,H)
    const float* Wh    = (const float*)d_in[2];  // (H,H)
    const float* Wq    = (const float*)d_in[3];  // (H,H)
    const float* v     = (const float*)d_in[4];  // (H,)

    float* out       = (float*)d_out;
    float* out_ctx   = out;            // (B,H)   = 8192 floats
    float* out_alpha = out + B_ * H_;  // (B,S)   = 131072 floats

    qproj_kernel  <<<dim3(H_ / 8, B_), 256>>>(query, Wq);
    score_gemm    <<<dim3(M_ / BM, NSLICE), 256>>>(enc, Wh, v);
    softmax_kernel<<<B_, 1024>>>(out_alpha);
    ctx_part_kernel<<<dim3(64, B_), 512>>>(enc, out_alpha);
    ctx_reduce_kernel<<<B_, 512>>>(out_ctx);
}

// round 5
// speedup vs baseline: 3.1630x; 3.1630x over previous
#include <cuda_runtime.h>
#include <math.h>
#include <stdint.h>

// Problem constants
#define B_  16
#define S_  8192
#define H_  512
#define M_  (B_ * S_)

// GEMM tiling
#define BM 128
#define BN 256
#define BK 32
#define NSLICE 2            // 512 / BN
#define NCHUNK 16           // 512 / BK
#define PAD 36              // smem row stride in floats (36 mod 32 == 4 -> conflict-free frags)

// ---------------- scratch ----------------
__device__ float g_qproj[B_ * H_];         // (B,H)
__device__ float g_part[NSLICE][M_];       // score partials per N-slice
__device__ float g_ctxpart[64][B_][H_];    // context partials

// ---------------- helpers ----------------
__device__ __forceinline__ uint32_t s2u(const void* p) {
    uint32_t a;
    asm("{ .reg .u64 t; cvta.to.shared.u64 t, %1; cvt.u32.u64 %0, t; }" : "=r"(a) : "l"(p));
    return a;
}
#define CP_ASYNC16(dst, src) \
    asm volatile("cp.async.cg.shared.global [%0], [%1], 16;" :: "r"(dst), "l"(src) : "memory")
#define CP_COMMIT()  asm volatile("cp.async.commit_group;" ::: "memory")
#define CP_WAIT1()   asm volatile("cp.async.wait_group 1;" ::: "memory")
#define CP_WAIT0()   asm volatile("cp.async.wait_group 0;" ::: "memory")

__device__ __forceinline__ void mma_tf32(float* d, const uint32_t* a, const uint32_t* b) {
    asm volatile(
        "mma.sync.aligned.m16n8k8.row.col.f32.tf32.tf32.f32 "
        "{%0,%1,%2,%3}, {%4,%5,%6,%7}, {%8,%9}, {%0,%1,%2,%3};"
        : "+f"(d[0]), "+f"(d[1]), "+f"(d[2]), "+f"(d[3])
        : "r"(a[0]), "r"(a[1]), "r"(a[2]), "r"(a[3]), "r"(b[0]), "r"(b[1]));
}

// ---------------- SMEM layout (dynamic) ----------------
// [0,1024)        sq (256 floats)
// [1024,2048)     sv (256 floats)
// [2048,4096)     red (128*4 floats)
// [4096,...)      A stages: 2 x 128*PAD*4 = 2 x 18432
// [40960,...)     B stages: 2 x 256*PAD*4 = 2 x 36864
#define SM_A      4096
#define SM_B      40960
#define A_STAGE   (BM * PAD * 4)      // 18432
#define B_STAGE   (BN * PAD * 4)      // 36864
#define SMEM_TOTAL (SM_B + 2 * B_STAGE)  // 114688

// ---------------- kernel 1: q_proj ----------------
__global__ void qproj_kernel(const float* __restrict__ query,
                             const float* __restrict__ Wq)
{
    int w = threadIdx.x >> 5, lane = threadIdx.x & 31;
    int o = blockIdx.x * 8 + w;
    int b = blockIdx.y;
    const float* q  = query + b * H_;
    const float* wr = Wq + o * H_;
    float s = 0.f;
    #pragma unroll 4
    for (int k = lane; k < H_; k += 32) s += q[k] * wr[k];
    #pragma unroll
    for (int off = 16; off > 0; off >>= 1) s += __shfl_xor_sync(0xffffffffu, s, off);
    if (lane == 0) g_qproj[b * H_ + o] = s;
}

// ---------------- kernel 2: tf32 mma.sync GEMM + fused tanh/v epilogue ----------------
// C[m,o] = sum_k enc[m,k] * Wh[o,k]
// g_part[slice][m] = sum_{o in slice} tanh(C[m,o] + qproj[b,o]) * v[o]
__global__ __launch_bounds__(256, 1)
void score_gemm(const float* __restrict__ A,     // enc (M_, 512)
                const float* __restrict__ Wh,    // (512, 512)
                const float* __restrict__ v)
{
    extern __shared__ char smem[];
    const uint32_t smem_u = s2u(smem);
    float* sq  = (float*)smem;
    float* sv  = sq + 256;
    float* red = sv + 256;                        // 128 x 4

    const int tid  = threadIdx.x;
    const int wid  = tid >> 5;
    const int lane = tid & 31;
    const int g    = lane >> 2;                   // group id (row)
    const int c    = lane & 3;                    // thread in group (col)
    const int wm   = wid & 1;                     // 2 warps over M
    const int wn   = wid >> 1;                    // 4 warps over N

    const int bm    = blockIdx.x;
    const int slice = blockIdx.y;
    const int m0    = bm * BM;
    const int n0    = slice * BN;
    const int b     = m0 >> 13;

    for (int j = tid; j < 256; j += 256) {
        sq[j] = g_qproj[b * H_ + n0 + j];
        sv[j] = v[n0 + j];
    }

    // accumulators: 4 m-frags x 8 n-frags x 4 regs
    float acc[4][8][4];
    #pragma unroll
    for (int i = 0; i < 4; i++)
        #pragma unroll
        for (int j = 0; j < 8; j++)
            #pragma unroll
            for (int k = 0; k < 4; k++) acc[i][j][k] = 0.f;

    const float* Abase = A + (size_t)m0 * H_;
    const float* Bbase = Wh + (size_t)n0 * H_;

    auto load_chunk = [&](int kc, int st) {
        const uint32_t abase = smem_u + SM_A + st * A_STAGE;
        const uint32_t bbase = smem_u + SM_B + st * B_STAGE;
        const float* As = Abase + kc * BK;
        const float* Bs = Bbase + kc * BK;
        #pragma unroll
        for (int i = 0; i < 4; i++) {             // A: 1024 chunks of 16B
            int id = tid + i * 256;
            int r = id >> 3, u = id & 7;
            CP_ASYNC16(abase + r * (PAD * 4) + u * 16, As + (size_t)r * H_ + u * 4);
        }
        #pragma unroll
        for (int i = 0; i < 8; i++) {             // B: 2048 chunks
            int id = tid + i * 256;
            int r = id >> 3, u = id & 7;
            CP_ASYNC16(bbase + r * (PAD * 4) + u * 16, Bs + (size_t)r * H_ + u * 4);
        }
        CP_COMMIT();
    };

    load_chunk(0, 0);

    int st = 0;
    #pragma unroll 1
    for (int kc = 0; kc < NCHUNK; kc++) {
        if (kc + 1 < NCHUNK) { load_chunk(kc + 1, st ^ 1); CP_WAIT1(); }
        else                 { CP_WAIT0(); }
        __syncthreads();

        const float* As = (const float*)(smem + SM_A + st * A_STAGE);
        const float* Bs = (const float*)(smem + SM_B + st * B_STAGE);

        #pragma unroll
        for (int ks = 0; ks < 4; ks++) {
            const int k0 = ks * 8;
            uint32_t afr[4][4];
            #pragma unroll
            for (int mf = 0; mf < 4; mf++) {
                const float* ap = As + (wm * 64 + mf * 16 + g) * PAD + k0 + c;
                afr[mf][0] = __float_as_uint(ap[0]);
                afr[mf][1] = __float_as_uint(ap[8 * PAD]);
                afr[mf][2] = __float_as_uint(ap[4]);
                afr[mf][3] = __float_as_uint(ap[8 * PAD + 4]);
            }
            uint32_t bfr[8][2];
            #pragma unroll
            for (int nf = 0; nf < 8; nf++) {
                const float* bp = Bs + (wn * 64 + nf * 8 + g) * PAD + k0 + c;
                bfr[nf][0] = __float_as_uint(bp[0]);
                bfr[nf][1] = __float_as_uint(bp[4]);
            }
            #pragma unroll
            for (int mf = 0; mf < 4; mf++)
                #pragma unroll
                for (int nf = 0; nf < 8; nf++)
                    mma_tf32(acc[mf][nf], afr[mf], bfr[nf]);
        }
        __syncthreads();
        st ^= 1;
    }

    // ---- epilogue: tanh(C + q) * v, reduce over this CTA's 256 columns ----
    float rowsum[8];
    #pragma unroll
    for (int i = 0; i < 8; i++) rowsum[i] = 0.f;

    #pragma unroll
    for (int mf = 0; mf < 4; mf++) {
        #pragma unroll
        for (int nf = 0; nf < 8; nf++) {
            const int cb = wn * 64 + nf * 8 + 2 * c;   // slice-local column
            const float q0 = sq[cb],     v0 = sv[cb];
            const float q1 = sq[cb + 1], v1 = sv[cb + 1];
            rowsum[mf * 2 + 0] += tanhf(acc[mf][nf][0] + q0) * v0
                                + tanhf(acc[mf][nf][1] + q1) * v1;
            rowsum[mf * 2 + 1] += tanhf(acc[mf][nf][2] + q0) * v0
                                + tanhf(acc[mf][nf][3] + q1) * v1;
        }
    }
    // reduce across the 4-thread column groups
    #pragma unroll
    for (int i = 0; i < 8; i++) {
        rowsum[i] += __shfl_xor_sync(0xffffffffu, rowsum[i], 1);
        rowsum[i] += __shfl_xor_sync(0xffffffffu, rowsum[i], 2);
    }
    if (c == 0) {
        #pragma unroll
        for (int i = 0; i < 8; i++) {
            const int mf = i >> 1, h = i & 1;
            const int row = wm * 64 + mf * 16 + g + h * 8;   // 0..127
            red[row * 4 + wn] = rowsum[i];
        }
    }
    __syncthreads();
    if (tid < BM) {
        const float s = red[tid * 4 + 0] + red[tid * 4 + 1]
                      + red[tid * 4 + 2] + red[tid * 4 + 3];
        g_part[slice][m0 + tid] = s;
    }
}

// ---------------- kernel 3: softmax ----------------
__global__ __launch_bounds__(1024)
void softmax_kernel(float* __restrict__ out_alpha)
{
    __shared__ float sm[32];
    const int b = blockIdx.x, tid = threadIdx.x;
    const int w = tid >> 5, lane = tid & 31;

    float sc[8];
    float mx = -1e30f;
    #pragma unroll
    for (int i = 0; i < 8; i++) {
        int m = b * S_ + tid + i * 1024;
        float x = g_part[0][m] + g_part[1][m];
        sc[i] = x;
        mx = fmaxf(mx, x);
    }
    #pragma unroll
    for (int off = 16; off > 0; off >>= 1) mx = fmaxf(mx, __shfl_xor_sync(0xffffffffu, mx, off));
    if (lane == 0) sm[w] = mx;
    __syncthreads();
    if (tid < 32) {
        float t = sm[tid];
        #pragma unroll
        for (int off = 16; off > 0; off >>= 1) t = fmaxf(t, __shfl_xor_sync(0xffffffffu, t, off));
        if (tid == 0) sm[0] = t;
    }
    __syncthreads();
    mx = sm[0];
    __syncthreads();

    float tot = 0.f;
    #pragma unroll
    for (int i = 0; i < 8; i++) { sc[i] = expf(sc[i] - mx); tot += sc[i]; }
    #pragma unroll
    for (int off = 16; off > 0; off >>= 1) tot += __shfl_xor_sync(0xffffffffu, tot, off);
    if (lane == 0) sm[w] = tot;
    __syncthreads();
    if (tid < 32) {
        float t = sm[tid];
        #pragma unroll
        for (int off = 16; off > 0; off >>= 1) t += __shfl_xor_sync(0xffffffffu, t, off);
        if (tid == 0) sm[0] = t;
    }
    __syncthreads();
    float inv = 1.f / sm[0];

    #pragma unroll
    for (int i = 0; i < 8; i++)
        out_alpha[b * S_ + tid + i * 1024] = sc[i] * inv;
}

// ---------------- kernel 4/5: context ----------------
__global__ __launch_bounds__(512)
void ctx_part_kernel(const float* __restrict__ enc,
                     const float* __restrict__ alpha)
{
    __shared__ float al[128];
    const int sch = blockIdx.x, b = blockIdx.y, h = threadIdx.x;
    const int s0 = sch * 128;
    if (threadIdx.x < 128) al[threadIdx.x] = alpha[b * S_ + s0 + threadIdx.x];
    __syncthreads();
    const float* e = enc + ((size_t)b * S_ + s0) * H_ + h;
    float acc = 0.f;
    #pragma unroll 8
    for (int s = 0; s < 128; s++) acc += al[s] * e[(size_t)s * H_];
    g_ctxpart[sch][b][h] = acc;
}

__global__ __launch_bounds__(512)
void ctx_reduce_kernel(float* __restrict__ out_ctx)
{
    const int b = blockIdx.x, h = threadIdx.x;
    float s = 0.f;
    #pragma unroll
    for (int cidx = 0; cidx < 64; cidx++) s += g_ctxpart[cidx][b][h];
    out_ctx[b * H_ + h] = s;
}

// ---------------- launcher ----------------
extern "C" void kernel_launch(void* const* d_in, const int* in_sizes, int n_in,
                              void* d_out, int out_size)
{
    const float* enc   = (const float*)d_in[0];
    const float* query = (const float*)d_in[1];
    const float* Wh    = (const float*)d_in[2];
    const float* Wq    = (const float*)d_in[3];
    const float* v     = (const float*)d_in[4];

    float* out       = (float*)d_out;
    float* out_ctx   = out;
    float* out_alpha = out + B_ * H_;

    cudaFuncSetAttribute(score_gemm, cudaFuncAttributeMaxDynamicSharedMemorySize, SMEM_TOTAL);

    qproj_kernel   <<<dim3(H_ / 8, B_), 256>>>(query, Wq);
    score_gemm     <<<dim3(M_ / BM, NSLICE), 256, SMEM_TOTAL>>>(enc, Wh, v);
    softmax_kernel <<<B_, 1024>>>(out_alpha);
    ctx_part_kernel<<<dim3(64, B_), 512>>>(enc, out_alpha);
    ctx_reduce_kernel<<<B_, 512>>>(out_ctx);
}

// round 8
// speedup vs baseline: 3.4956x; 1.1051x over previous
#include <cuda_runtime.h>
#include <math.h>
#include <stdint.h>

// Problem constants
#define B_  16
#define S_  8192
#define H_  512
#define M_  (B_ * S_)

// GEMM tiling
#define BM 128
#define BN 128
#define BK 32
#define NSLICE 4            // 512 / BN
#define NCHUNK 16           // 512 / BK
#define PAD 36              // smem row stride in floats

// ---------------- scratch ----------------
__device__ float g_qproj[B_ * H_];         // (B,H)
__device__ float g_part[NSLICE][M_];       // score partials per N-slice
__device__ float g_ctxpart[64][B_][H_];    // context partials

// ---------------- helpers ----------------
__device__ __forceinline__ uint32_t s2u(const void* p) {
    uint32_t a;
    asm("{ .reg .u64 t; cvta.to.shared.u64 t, %1; cvt.u32.u64 %0, t; }" : "=r"(a) : "l"(p));
    return a;
}
#define CP_ASYNC16(dst, src) \
    asm volatile("cp.async.cg.shared.global [%0], [%1], 16;" :: "r"(dst), "l"(src) : "memory")
#define CP_COMMIT()  asm volatile("cp.async.commit_group;" ::: "memory")
#define CP_WAIT1()   asm volatile("cp.async.wait_group 1;" ::: "memory")
#define CP_WAIT0()   asm volatile("cp.async.wait_group 0;" ::: "memory")

__device__ __forceinline__ void mma_tf32(float* d, const uint32_t* a, const uint32_t* b) {
    asm volatile(
        "mma.sync.aligned.m16n8k8.row.col.f32.tf32.tf32.f32 "
        "{%0,%1,%2,%3}, {%4,%5,%6,%7}, {%8,%9}, {%0,%1,%2,%3};"
        : "+f"(d[0]), "+f"(d[1]), "+f"(d[2]), "+f"(d[3])
        : "r"(a[0]), "r"(a[1]), "r"(a[2]), "r"(a[3]), "r"(b[0]), "r"(b[1]));
}

// ---------------- SMEM layout (dynamic) ----------------
// [0,512)     sq (128 floats)
// [512,1024)  sv (128 floats)
// [1024,3072) red (128*4 floats)
// [3072,...)  A stages: 2 x 128*PAD*4 = 2 x 18432
// [39936,...) B stages: 2 x 18432
#define SM_A      3072
#define A_STAGE   (BM * PAD * 4)          // 18432
#define SM_B      (SM_A + 2 * A_STAGE)    // 39936
#define B_STAGE   (BN * PAD * 4)          // 18432
#define SMEM_TOTAL (SM_B + 2 * B_STAGE)   // 76800  -> 2 CTAs/SM

// ---------------- kernel 1: q_proj ----------------
__global__ void qproj_kernel(const float* __restrict__ query,
                             const float* __restrict__ Wq)
{
    int w = threadIdx.x >> 5, lane = threadIdx.x & 31;
    int o = blockIdx.x * 8 + w;
    int b = blockIdx.y;
    const float* q  = query + b * H_;
    const float* wr = Wq + o * H_;
    float s = 0.f;
    #pragma unroll 4
    for (int k = lane; k < H_; k += 32) s += q[k] * wr[k];
    #pragma unroll
    for (int off = 16; off > 0; off >>= 1) s += __shfl_xor_sync(0xffffffffu, s, off);
    if (lane == 0) g_qproj[b * H_ + o] = s;
}

// ---------------- kernel 2: tf32 mma.sync GEMM + fused tanh/v epilogue ----------------
__global__ __launch_bounds__(256, 2)
void score_gemm(const float* __restrict__ A,     // enc (M_, 512)
                const float* __restrict__ Wh,    // (512, 512)
                const float* __restrict__ v)
{
    extern __shared__ char smem[];
    const uint32_t smem_u = s2u(smem);
    float* sq  = (float*)smem;            // 128
    float* sv  = sq + 128;                // 128
    float* red = sv + 128;                // 128 x 4

    const int tid  = threadIdx.x;
    const int wid  = tid >> 5;
    const int lane = tid & 31;
    const int g    = lane >> 2;           // row in frag
    const int c    = lane & 3;            // col group
    const int wm   = wid & 1;             // 2 warps over M (64 rows each)
    const int wn   = wid >> 1;            // 4 warps over N (32 cols each)

    const int bm    = blockIdx.x;
    const int slice = blockIdx.y;
    const int m0    = bm * BM;
    const int n0    = slice * BN;
    const int b     = m0 >> 13;

    if (tid < 128) {
        sq[tid] = g_qproj[b * H_ + n0 + tid];
        sv[tid] = v[n0 + tid];
    }

    // accumulators: 4 m-frags x 4 n-frags x 4 regs
    float acc[4][4][4];
    #pragma unroll
    for (int i = 0; i < 4; i++)
        #pragma unroll
        for (int j = 0; j < 4; j++)
            #pragma unroll
            for (int k = 0; k < 4; k++) acc[i][j][k] = 0.f;

    const float* Abase = A + (size_t)m0 * H_;
    const float* Bbase = Wh + (size_t)n0 * H_;

    auto load_chunk = [&](int kc, int st) {
        const uint32_t abase = smem_u + SM_A + st * A_STAGE;
        const uint32_t bbase = smem_u + SM_B + st * B_STAGE;
        const float* As = Abase + kc * BK;
        const float* Bs = Bbase + kc * BK;
        #pragma unroll
        for (int i = 0; i < 4; i++) {             // A: 1024 16B units
            int id = tid + i * 256;
            int r = id >> 3, u = id & 7;
            CP_ASYNC16(abase + r * (PAD * 4) + u * 16, As + (size_t)r * H_ + u * 4);
        }
        #pragma unroll
        for (int i = 0; i < 4; i++) {             // B: 1024 16B units
            int id = tid + i * 256;
            int r = id >> 3, u = id & 7;
            CP_ASYNC16(bbase + r * (PAD * 4) + u * 16, Bs + (size_t)r * H_ + u * 4);
        }
        CP_COMMIT();
    };

    load_chunk(0, 0);

    int st = 0;
    #pragma unroll 1
    for (int kc = 0; kc < NCHUNK; kc++) {
        if (kc + 1 < NCHUNK) { load_chunk(kc + 1, st ^ 1); CP_WAIT1(); }
        else                 { CP_WAIT0(); }
        __syncthreads();

        const float* As = (const float*)(smem + SM_A + st * A_STAGE);
        const float* Bs = (const float*)(smem + SM_B + st * B_STAGE);

        #pragma unroll
        for (int ks = 0; ks < 4; ks++) {
            const int k0 = ks * 8;
            uint32_t afr[4][4];
            #pragma unroll
            for (int mf = 0; mf < 4; mf++) {
                const float* ap = As + (wm * 64 + mf * 16 + g) * PAD + k0 + c;
                afr[mf][0] = __float_as_uint(ap[0]);
                afr[mf][1] = __float_as_uint(ap[8 * PAD]);
                afr[mf][2] = __float_as_uint(ap[4]);
                afr[mf][3] = __float_as_uint(ap[8 * PAD + 4]);
            }
            uint32_t bfr[4][2];
            #pragma unroll
            for (int nf = 0; nf < 4; nf++) {
                const float* bp = Bs + (wn * 32 + nf * 8 + g) * PAD + k0 + c;
                bfr[nf][0] = __float_as_uint(bp[0]);
                bfr[nf][1] = __float_as_uint(bp[4]);
            }
            #pragma unroll
            for (int mf = 0; mf < 4; mf++)
                #pragma unroll
                for (int nf = 0; nf < 4; nf++)
                    mma_tf32(acc[mf][nf], afr[mf], bfr[nf]);
        }
        __syncthreads();
        st ^= 1;
    }

    // ---- epilogue: tanh(C + q) * v, reduce over this CTA's 128 columns ----
    float rowsum[8];
    #pragma unroll
    for (int i = 0; i < 8; i++) rowsum[i] = 0.f;

    #pragma unroll
    for (int mf = 0; mf < 4; mf++) {
        #pragma unroll
        for (int nf = 0; nf < 4; nf++) {
            const int cb = wn * 32 + nf * 8 + 2 * c;   // slice-local column
            const float q0 = sq[cb],     v0 = sv[cb];
            const float q1 = sq[cb + 1], v1 = sv[cb + 1];
            rowsum[mf * 2 + 0] += tanhf(acc[mf][nf][0] + q0) * v0
                                + tanhf(acc[mf][nf][1] + q1) * v1;
            rowsum[mf * 2 + 1] += tanhf(acc[mf][nf][2] + q0) * v0
                                + tanhf(acc[mf][nf][3] + q1) * v1;
        }
    }
    #pragma unroll
    for (int i = 0; i < 8; i++) {
        rowsum[i] += __shfl_xor_sync(0xffffffffu, rowsum[i], 1);
        rowsum[i] += __shfl_xor_sync(0xffffffffu, rowsum[i], 2);
    }
    if (c == 0) {
        #pragma unroll
        for (int i = 0; i < 8; i++) {
            const int mf = i >> 1, h = i & 1;
            const int row = wm * 64 + mf * 16 + g + h * 8;   // 0..127
            red[row * 4 + wn] = rowsum[i];
        }
    }
    __syncthreads();
    if (tid < BM) {
        g_part[slice][m0 + tid] = red[tid * 4 + 0] + red[tid * 4 + 1]
                                + red[tid * 4 + 2] + red[tid * 4 + 3];
    }
}

// ---------------- kernel 3: softmax ----------------
__global__ __launch_bounds__(1024)
void softmax_kernel(float* __restrict__ out_alpha)
{
    __shared__ float sm[32];
    const int b = blockIdx.x, tid = threadIdx.x;
    const int w = tid >> 5, lane = tid & 31;

    float sc[8];
    float mx = -1e30f;
    #pragma unroll
    for (int i = 0; i < 8; i++) {
        int m = b * S_ + tid + i * 1024;
        float x = g_part[0][m] + g_part[1][m] + g_part[2][m] + g_part[3][m];
        sc[i] = x;
        mx = fmaxf(mx, x);
    }
    #pragma unroll
    for (int off = 16; off > 0; off >>= 1) mx = fmaxf(mx, __shfl_xor_sync(0xffffffffu, mx, off));
    if (lane == 0) sm[w] = mx;
    __syncthreads();
    if (tid < 32) {
        float t = sm[tid];
        #pragma unroll
        for (int off = 16; off > 0; off >>= 1) t = fmaxf(t, __shfl_xor_sync(0xffffffffu, t, off));
        if (tid == 0) sm[0] = t;
    }
    __syncthreads();
    mx = sm[0];
    __syncthreads();

    float tot = 0.f;
    #pragma unroll
    for (int i = 0; i < 8; i++) { sc[i] = expf(sc[i] - mx); tot += sc[i]; }
    #pragma unroll
    for (int off = 16; off > 0; off >>= 1) tot += __shfl_xor_sync(0xffffffffu, tot, off);
    if (lane == 0) sm[w] = tot;
    __syncthreads();
    if (tid < 32) {
        float t = sm[tid];
        #pragma unroll
        for (int off = 16; off > 0; off >>= 1) t += __shfl_xor_sync(0xffffffffu, t, off);
        if (tid == 0) sm[0] = t;
    }
    __syncthreads();
    float inv = 1.f / sm[0];

    #pragma unroll
    for (int i = 0; i < 8; i++)
        out_alpha[b * S_ + tid + i * 1024] = sc[i] * inv;
}

// ---------------- kernel 4: context partials (float4 per thread) ----------------
__global__ __launch_bounds__(128)
void ctx_part_kernel(const float* __restrict__ enc,
                     const float* __restrict__ alpha)
{
    __shared__ float al[128];
    const int sch = blockIdx.x, b = blockIdx.y;
    const int tid = threadIdx.x;               // 0..127 -> H/4 float4 lanes
    const int s0  = sch * 128;
    al[tid] = alpha[b * S_ + s0 + tid];
    __syncthreads();
    const float4* e = (const float4*)(enc + ((size_t)b * S_ + s0) * H_) + tid;
    float4 acc = make_float4(0.f, 0.f, 0.f, 0.f);
    #pragma unroll 8
    for (int s = 0; s < 128; s++) {
        float4 t = e[(size_t)s * (H_ / 4)];
        float  w = al[s];
        acc.x += w * t.x; acc.y += w * t.y;
        acc.z += w * t.z; acc.w += w * t.w;
    }
    ((float4*)&g_ctxpart[sch][b][0])[tid] = acc;
}

// ---------------- kernel 5: reduce context partials ----------------
__global__ __launch_bounds__(512)
void ctx_reduce_kernel(float* __restrict__ out_ctx)
{
    const int b = blockIdx.x, h = threadIdx.x;
    float s = 0.f;
    #pragma unroll
    for (int cidx = 0; cidx < 64; cidx++) s += g_ctxpart[cidx][b][h];
    out_ctx[b * H_ + h] = s;
}

// ---------------- launcher ----------------
extern "C" void kernel_launch(void* const* d_in, const int* in_sizes, int n_in,
                              void* d_out, int out_size)
{
    const float* enc   = (const float*)d_in[0];
    const float* query = (const float*)d_in[1];
    const float* Wh    = (const float*)d_in[2];
    const float* Wq    = (const float*)d_in[3];
    const float* v     = (const float*)d_in[4];

    float* out       = (float*)d_out;
    float* out_ctx   = out;
    float* out_alpha = out + B_ * H_;

    cudaFuncSetAttribute(score_gemm, cudaFuncAttributeMaxDynamicSharedMemorySize, SMEM_TOTAL);

    qproj_kernel   <<<dim3(H_ / 8, B_), 256>>>(query, Wq);
    score_gemm     <<<dim3(M_ / BM, NSLICE), 256, SMEM_TOTAL>>>(enc, Wh, v);
    softmax_kernel <<<B_, 1024>>>(out_alpha);
    ctx_part_kernel<<<dim3(64, B_), 128>>>(enc, out_alpha);
    ctx_reduce_kernel<<<B_, 512>>>(out_ctx);
}